// round 11
// baseline (speedup 1.0000x reference)
#include <cuda_runtime.h>
#include <cuda_bf16.h>
#include <math.h>
#include <stdint.h>

// ---------------------------------------------------------------------------
// Fused per-graph GNN: 5x TAGConv(K=2) + ReLU + gated softmax pooling.
// One CTA per graph (5000 CTAs, 256 threads). All features in shared memory.
//
// R11 = R8 + half-redundancy GEMM:
//   - GEMM on warps 0-3 only; each warp owns 2 m-tiles x ALL n-tiles.
//     Weight fragments now loaded 4x per CTA (was 8x); activation hi/lo
//     conversion still exactly once per element (m-tiles partition rows).
//   - warps 4-7 do the pad zero-fill concurrently with the epilogue.
//   - prop / numerics identical to R8 (3xBF16 m16n8k16, pre-scaled h~).
// ---------------------------------------------------------------------------

#define NODES   100
#define EDGES   400
#define NTHR    256
#define ST      84      // smem row stride (floats); 84 mod 32 = 20 -> conflict-free
#define MROWS   128     // 8 m-tiles * 16

__device__ __forceinline__ uint32_t pack_bf16x2(float lo, float hi) {
    uint32_t r;
    asm("cvt.rn.bf16x2.f32 %0, %1, %2;" : "=r"(r) : "f"(hi), "f"(lo));
    return r;
}

__device__ __forceinline__ void mma_bf16(float c[4], const uint32_t a[4],
                                         uint32_t b0, uint32_t b1) {
    asm("mma.sync.aligned.m16n8k16.row.col.f32.bf16.bf16.f32 "
        "{%0,%1,%2,%3}, {%4,%5,%6,%7}, {%8,%9}, {%0,%1,%2,%3};"
        : "+f"(c[0]), "+f"(c[1]), "+f"(c[2]), "+f"(c[3])
        : "r"(a[0]), "r"(a[1]), "r"(a[2]), "r"(a[3]), "r"(b0), "r"(b1));
}

// scale by iv then hi/lo split into two bf16x2 regs
__device__ __forceinline__ void split2s(float2 a, float iv,
                                        uint32_t& hi, uint32_t& lo) {
    a.x *= iv; a.y *= iv;
    hi = pack_bf16x2(a.x, a.y);
    float hx = __uint_as_float(hi << 16);
    float hy = __uint_as_float(hi & 0xFFFF0000u);
    lo = pack_bf16x2(a.x - hx, a.y - hy);
}

// ---- packed bf16 hi/lo weights in B-fragment order (layout as R7/R8) ------
// KT16 = {5,5,5,4,4}, NT = {9,9,8,7,5}; per-layer floats = 3*KT*NT*128
__device__ float g_Wpad[68352];

__global__ void prep_weights(const float* W0, const float* W1, const float* W2,
                             const float* W3, const float* W4) {
    const int DIN[5]  = {74, 70, 65, 60, 55};
    const int DOUT[5] = {70, 65, 60, 55, 37};
    const int KT[5]   = {5, 5, 5, 4, 4};
    const int NT[5]   = {9, 9, 8, 7, 5};
    const int OFF[6]  = {0, 17280, 34560, 49920, 60672, 68352};
    const float* Ws[5] = {W0, W1, W2, W3, W4};

    for (int idx = blockIdx.x * blockDim.x + threadIdx.x; idx < 68352;
         idx += gridDim.x * blockDim.x) {
        int l = 0;
        while (idx >= OFF[l + 1]) l++;
        int rel    = idx - OFF[l];
        int block  = rel >> 7;
        int within = rel & 127;
        int lane = within >> 2;
        int j    = within & 3;          // 0:b0hi 1:b1hi 2:b0lo 3:b1lo
        int pnb  = KT[l] * NT[l];
        int p    = block / pnb;
        int r    = block - p * pnb;
        int kt   = r / NT[l];
        int nt   = r - kt * NT[l];
        int k0   = kt * 16 + (lane & 3) * 2 + ((j & 1) ? 8 : 0);
        int col  = nt * 8 + (lane >> 2);
        float w0 = 0.f, w1 = 0.f;
        if (col < DOUT[l]) {
            if (k0     < DIN[l]) w0 = Ws[l][(p * DIN[l] + k0) * DOUT[l] + col];
            if (k0 + 1 < DIN[l]) w1 = Ws[l][(p * DIN[l] + k0 + 1) * DOUT[l] + col];
        }
        uint32_t packed;
        uint32_t hi = 0;
        asm("cvt.rn.bf16x2.f32 %0, %1, %2;" : "=r"(hi) : "f"(w1), "f"(w0));
        if (j < 2) {
            packed = hi;
        } else {
            float hx = __uint_as_float(hi << 16);
            float hy = __uint_as_float(hi & 0xFFFF0000u);
            asm("cvt.rn.bf16x2.f32 %0, %1, %2;"
                : "=r"(packed) : "f"(w1 - hy), "f"(w0 - hx));
        }
        g_Wpad[idx] = __uint_as_float(packed);
    }
}

struct SmemLayout {
    float buf0[MROWS * ST];
    float buf1[MROWS * ST];
    float nA[128];     // n = deg^-1/2
    float n2[128];     // n^2 (=1/d)
    float invn[128];   // 1/n (=sqrt d)
    float red[128];
    float gate[128];
    int   rowptr[104];
    int   cnt[128];
    unsigned short csr[EDGES];
};

// ---- propagation (R8 style): out~[v] = n2[v] * sum_e in~[src_e] -----------
template <int DINP>
__device__ __forceinline__ void prop(const float* __restrict__ in,
                                     float* __restrict__ outb,
                                     const float* __restrict__ n2,
                                     const int* __restrict__ rowptr,
                                     const unsigned short* __restrict__ csr,
                                     int tid) {
    constexpr int NG = DINP / 8;
    for (int task = tid; task < NODES * NG; task += NTHR) {
        int v  = task / NG;
        int g  = task - v * NG;
        int c0 = g * 8;
        float4 a0 = make_float4(0.f, 0.f, 0.f, 0.f);
        float4 a1 = make_float4(0.f, 0.f, 0.f, 0.f);
        int e0 = rowptr[v], e1 = rowptr[v + 1];
        for (int e = e0; e < e1; e++) {
            int s = csr[e];
            const float4* r = reinterpret_cast<const float4*>(in + s * ST + c0);
            float4 r0 = r[0], r1 = r[1];
            a0.x += r0.x; a0.y += r0.y; a0.z += r0.z; a0.w += r0.w;
            a1.x += r1.x; a1.y += r1.y; a1.z += r1.z; a1.w += r1.w;
        }
        float f = n2[v];
        a0.x *= f; a0.y *= f; a0.z *= f; a0.w *= f;
        a1.x *= f; a1.y *= f; a1.z *= f; a1.w *= f;
        float4* o = reinterpret_cast<float4*>(outb + v * ST + c0);
        o[0] = a0; o[1] = a1;
    }
}

// ---- GEMM pass (3xBF16): 2 m-tiles (rows wid*32..+31), ALL NT n-tiles -----
template <int KT, int NT>
__device__ __forceinline__ void gemm_mma(float (*C)[2][4],
                                         const float* __restrict__ H,
                                         const float* __restrict__ Wp,
                                         const float* __restrict__ invn,
                                         int wid, int lane) {
    int r0 = wid * 32 + (lane >> 2);
    float iv0 = invn[r0];
    float iv1 = invn[r0 + 8];
    float iv2 = invn[r0 + 16];
    float iv3 = invn[r0 + 24];
    const float* hb = H + r0 * ST + (lane & 3) * 2;
#pragma unroll
    for (int kt = 0; kt < KT; kt++) {
        const float* hm = hb + kt * 16;
        uint32_t ahi[2][4], alo[2][4];
        {   // m-tile 0: rows r0, r0+8
            float2 p0 = *reinterpret_cast<const float2*>(hm);
            float2 p1 = *reinterpret_cast<const float2*>(hm + 8 * ST);
            float2 p2 = *reinterpret_cast<const float2*>(hm + 8);
            float2 p3 = *reinterpret_cast<const float2*>(hm + 8 + 8 * ST);
            split2s(p0, iv0, ahi[0][0], alo[0][0]);
            split2s(p1, iv1, ahi[0][1], alo[0][1]);
            split2s(p2, iv0, ahi[0][2], alo[0][2]);
            split2s(p3, iv1, ahi[0][3], alo[0][3]);
        }
        {   // m-tile 1: rows r0+16, r0+24
            const float* hm1 = hm + 16 * ST;
            float2 p0 = *reinterpret_cast<const float2*>(hm1);
            float2 p1 = *reinterpret_cast<const float2*>(hm1 + 8 * ST);
            float2 p2 = *reinterpret_cast<const float2*>(hm1 + 8);
            float2 p3 = *reinterpret_cast<const float2*>(hm1 + 8 + 8 * ST);
            split2s(p0, iv2, ahi[1][0], alo[1][0]);
            split2s(p1, iv3, ahi[1][1], alo[1][1]);
            split2s(p2, iv2, ahi[1][2], alo[1][2]);
            split2s(p3, iv3, ahi[1][3], alo[1][3]);
        }
        const float4* wrow = reinterpret_cast<const float4*>(Wp) +
                             (size_t)kt * NT * 32 + lane;
#pragma unroll
        for (int nt = 0; nt < NT; nt++) {
            float4 w = __ldg(wrow + nt * 32);
            uint32_t bh0 = __float_as_uint(w.x);
            uint32_t bh1 = __float_as_uint(w.y);
            uint32_t bl0 = __float_as_uint(w.z);
            uint32_t bl1 = __float_as_uint(w.w);
#pragma unroll
            for (int m = 0; m < 2; m++) {
                mma_bf16(C[nt][m], ahi[m], bh0, bh1);
                mma_bf16(C[nt][m], ahi[m], bl0, bl1);
                mma_bf16(C[nt][m], alo[m], bh0, bh1);
            }
        }
    }
}

// ---- epilogue: bias + relu, scale by n[v]; 2 m-tiles per warp -------------
template <int NT, int DOUT>
__device__ __forceinline__ void epilogue(float (*C)[2][4],
                                         float* __restrict__ bufOut,
                                         const float* __restrict__ B,
                                         const float* __restrict__ nA,
                                         int wid, int lane) {
    int rb = wid * 32 + (lane >> 2);
    int cb = 2 * (lane & 3);
#pragma unroll
    for (int nt = 0; nt < NT; nt++) {
        int c = nt * 8 + cb;
        float b0v = (c     < DOUT) ? __ldg(B + c)     : 0.f;
        float b1v = (c + 1 < DOUT) ? __ldg(B + c + 1) : 0.f;
#pragma unroll
        for (int m = 0; m < 2; m++) {
            int r0 = rb + m * 16;
            float nv0 = (r0     < NODES) ? nA[r0]     : 0.f;
            float nv1 = (r0 + 8 < NODES) ? nA[r0 + 8] : 0.f;
            float v0 = (c     < DOUT) ? fmaxf(C[nt][m][0] + b0v, 0.f) * nv0 : 0.f;
            float v1 = (c + 1 < DOUT) ? fmaxf(C[nt][m][1] + b1v, 0.f) * nv0 : 0.f;
            if (r0 < NODES)
                *reinterpret_cast<float2*>(bufOut + r0 * ST + c) =
                    make_float2(v0, v1);
            float v2 = (c     < DOUT) ? fmaxf(C[nt][m][2] + b0v, 0.f) * nv1 : 0.f;
            float v3 = (c + 1 < DOUT) ? fmaxf(C[nt][m][3] + b1v, 0.f) * nv1 : 0.f;
            if (r0 + 8 < NODES)
                *reinterpret_cast<float2*>(bufOut + (r0 + 8) * ST + c) =
                    make_float2(v2, v3);
        }
    }
}

// ---- one TAGConv layer ----------------------------------------------------
template <int KT, int NT, int DOUT, int ZLO, int ZHI>
__device__ __forceinline__ void layer(float* bufIn, float* bufOut,
                                      const float* __restrict__ Wp,
                                      const float* __restrict__ B,
                                      SmemLayout* sm, int tid) {
    constexpr int DINP = KT * 16;
    constexpr int PSZ  = KT * NT * 128;
    int wid  = tid >> 5;
    int lane = tid & 31;

    // U~ -> bufOut (all 8 warps)
    prop<DINP>(bufIn, bufOut, sm->n2, sm->rowptr, sm->csr, tid);
    __syncthreads();

    float C[NT][2][4];
    if (wid < 4) {
#pragma unroll
        for (int nt = 0; nt < NT; nt++)
#pragma unroll
            for (int m = 0; m < 2; m++)
#pragma unroll
                for (int i = 0; i < 4; i++) C[nt][m][i] = 0.f;
        gemm_mma<KT, NT>(C, bufIn,  Wp,       sm->invn, wid, lane);  // h @ Wa
        gemm_mma<KT, NT>(C, bufOut, Wp + PSZ, sm->invn, wid, lane);  // U @ Wb
    }
    __syncthreads();

    // V~ -> bufIn (h dead; all 8 warps)
    prop<DINP>(bufOut, bufIn, sm->n2, sm->rowptr, sm->csr, tid);
    __syncthreads();

    if (wid < 4) {
        gemm_mma<KT, NT>(C, bufIn, Wp + 2 * PSZ, sm->invn, wid, lane); // V @ Wc
        epilogue<NT, DOUT>(C, bufOut, B, sm->nA, wid, lane);
    } else if (ZHI > ZLO) {
        // warps 4-7: zero pad cols [ZLO, ZHI) concurrently (disjoint cols)
        constexpr int ZW = ZHI - ZLO;
        for (int idx = tid - 128; idx < NODES * ZW; idx += 128) {
            int r = idx / ZW;
            int c = ZLO + (idx - r * ZW);
            bufOut[r * ST + c] = 0.f;
        }
    }
    __syncthreads();
}

__global__ void __launch_bounds__(NTHR, 2)
gnn_fused_kernel(const float* __restrict__ x,
                 const int* __restrict__ src,
                 const int* __restrict__ dst,
                 const float* __restrict__ b0, const float* __restrict__ b1,
                 const float* __restrict__ b2, const float* __restrict__ b3,
                 const float* __restrict__ b4,
                 const float* __restrict__ gw, const float* __restrict__ gb,
                 float* __restrict__ out) {
    extern __shared__ char smem_raw[];
    SmemLayout* sm = reinterpret_cast<SmemLayout*>(smem_raw);
    const int tid = threadIdx.x;
    const int g   = blockIdx.x;

    float* A = sm->buf0;
    float* B = sm->buf1;

    // ---- zero both feature buffers (pad invariant)
    {
        float4* z = reinterpret_cast<float4*>(sm->buf0);
        const int nq = 2 * MROWS * ST / 4;
        for (int i = tid; i < nq; i += NTHR)
            z[i] = make_float4(0.f, 0.f, 0.f, 0.f);
    }
    if (tid < 128) sm->cnt[tid] = 0;
    __syncthreads();

    // ---- degree count
    const int* srcg = src + g * EDGES;
    const int* dstg = dst + g * EDGES;
    const int base = g * NODES;
    for (int e = tid; e < EDGES; e += NTHR) {
        int dl = dstg[e] - base;
        atomicAdd(&sm->cnt[dl], 1);
    }
    __syncthreads();

    if (tid < 128) {
        float d = fmaxf((float)sm->cnt[tid], 1.f);
        sm->nA[tid]   = rsqrtf(d);
        sm->n2[tid]   = 1.0f / d;
        sm->invn[tid] = sqrtf(d);
    }
    for (int off = 1; off < 128; off <<= 1) {       // inclusive scan
        int t = 0;
        if (tid < 128 && tid >= off) t = sm->cnt[tid - off];
        __syncthreads();
        if (tid < 128 && tid >= off) sm->cnt[tid] += t;
        __syncthreads();
    }
    if (tid == 0) sm->rowptr[0] = 0;
    if (tid < NODES) sm->rowptr[tid + 1] = sm->cnt[tid];
    __syncthreads();
    if (tid < NODES) sm->cnt[tid] = sm->rowptr[tid];
    __syncthreads();
    for (int e = tid; e < EDGES; e += NTHR) {
        int sl = srcg[e] - base;
        int dl = dstg[e] - base;
        int pos = atomicAdd(&sm->cnt[dl], 1);
        sm->csr[pos] = (unsigned short)sl;
    }
    __syncthreads();

    // ---- load pre-scaled x~ = n (.) x
    {
        const float* xg = x + (size_t)g * (NODES * 74);
        for (int idx = tid; idx < NODES * 74; idx += NTHR) {
            int v = idx / 74;
            int c = idx - v * 74;
            A[v * ST + c] = xg[idx] * sm->nA[v];
        }
    }
    __syncthreads();

    // ---- 5 TAGConv layers    KT NT DOUT ZLO ZHI       Wpad offset
    layer<5, 9, 70, 72, 80>(A, B, g_Wpad +     0, b0, sm, tid);
    layer<5, 9, 65, 72, 80>(B, A, g_Wpad + 17280, b1, sm, tid);
    layer<5, 8, 60, 64, 64>(A, B, g_Wpad + 34560, b2, sm, tid);
    layer<4, 7, 55, 56, 64>(B, A, g_Wpad + 49920, b3, sm, tid);
    layer<4, 5, 37, 40, 40>(A, B, g_Wpad + 60672, b4, sm, tid);
    float* H = B;   // final h~ = n (.) h : 100 x 37 (cols 37..39 zero)

    // ---- gate = invn * (h~ @ gw) + gb ; softmax; pool
    float gval = -1e30f;
    if (tid < NODES) {
        float s = 0.f;
#pragma unroll
        for (int c = 0; c < 37; c++)
            s += H[tid * ST + c] * __ldg(gw + c);
        s = s * sm->invn[tid] + __ldg(gb);
        sm->gate[tid] = s;
        gval = s;
    }
    if (tid < 128) sm->red[tid] = gval;
    __syncthreads();
    for (int s = 64; s > 0; s >>= 1) {
        if (tid < s) sm->red[tid] = fmaxf(sm->red[tid], sm->red[tid + s]);
        __syncthreads();
    }
    float gmax = sm->red[0];
    __syncthreads();

    float ev = 0.f;
    if (tid < NODES) {
        ev = expf(sm->gate[tid] - gmax);
        sm->gate[tid] = ev * sm->invn[tid];   // fold invn for pooled h~ sum
    }
    if (tid < 128) sm->red[tid] = ev;
    __syncthreads();
    for (int s = 64; s > 0; s >>= 1) {
        if (tid < s) sm->red[tid] += sm->red[tid + s];
        __syncthreads();
    }
    float Z = sm->red[0];

    if (tid < 37) {
        float a = 0.f;
        for (int v = 0; v < NODES; v++)
            a += sm->gate[v] * H[v * ST + tid];
        out[g * 37 + tid] = a / Z;
    }
}

extern "C" void kernel_launch(void* const* d_in, const int* in_sizes, int n_in,
                              void* d_out, int out_size) {
    const float* x   = (const float*)d_in[0];
    const int*   src = (const int*)d_in[1];
    const int*   dst = (const int*)d_in[2];
    const float* W0 = (const float*)d_in[4];
    const float* b0 = (const float*)d_in[5];
    const float* W1 = (const float*)d_in[6];
    const float* b1 = (const float*)d_in[7];
    const float* W2 = (const float*)d_in[8];
    const float* b2 = (const float*)d_in[9];
    const float* W3 = (const float*)d_in[10];
    const float* b3 = (const float*)d_in[11];
    const float* W4 = (const float*)d_in[12];
    const float* b4 = (const float*)d_in[13];
    const float* gw = (const float*)d_in[14];
    const float* gb = (const float*)d_in[15];
    float* out = (float*)d_out;

    prep_weights<<<128, 256>>>(W0, W1, W2, W3, W4);

    const int smem_bytes = (int)sizeof(SmemLayout);
    cudaFuncSetAttribute(gnn_fused_kernel,
                         cudaFuncAttributeMaxDynamicSharedMemorySize,
                         smem_bytes);
    gnn_fused_kernel<<<5000, NTHR, smem_bytes>>>(
        x, src, dst,
        b0, b1, b2, b3, b4,
        gw, gb, out);
}

// round 12
// speedup vs baseline: 1.3415x; 1.3415x over previous
#include <cuda_runtime.h>
#include <cuda_bf16.h>
#include <math.h>
#include <stdint.h>

// ---------------------------------------------------------------------------
// Fused per-graph GNN: 5x TAGConv(K=2) + ReLU + gated softmax pooling.
// One CTA per graph (5000 CTAs, 256 threads). All features in shared memory.
//
// R12 = R8 minus the dead m-tile:
//   - 100 nodes need only 7 m-tiles (112 rows); R8's 8th m-tile (rows
//     112-127) was pure padding whose results were never stored. GEMM +
//     epilogue now run on warps 0-6; warp 7 zero-fills pad columns
//     concurrently with gemm_V/epilogue. -12.5% weight LDG / cvt / MMA.
//   - everything else identical to R8 (3xBF16 m16n8k16, pre-scaled h~).
// ---------------------------------------------------------------------------

#define NODES   100
#define EDGES   400
#define NTHR    256
#define ST      84      // smem row stride (floats); 84 mod 32 = 20 -> conflict-free
#define MROWS   112     // 7 m-tiles * 16

__device__ __forceinline__ uint32_t pack_bf16x2(float lo, float hi) {
    uint32_t r;
    asm("cvt.rn.bf16x2.f32 %0, %1, %2;" : "=r"(r) : "f"(hi), "f"(lo));
    return r;
}

__device__ __forceinline__ void mma_bf16(float c[4], const uint32_t a[4],
                                         uint32_t b0, uint32_t b1) {
    asm("mma.sync.aligned.m16n8k16.row.col.f32.bf16.bf16.f32 "
        "{%0,%1,%2,%3}, {%4,%5,%6,%7}, {%8,%9}, {%0,%1,%2,%3};"
        : "+f"(c[0]), "+f"(c[1]), "+f"(c[2]), "+f"(c[3])
        : "r"(a[0]), "r"(a[1]), "r"(a[2]), "r"(a[3]), "r"(b0), "r"(b1));
}

// scale by iv then hi/lo split into two bf16x2 regs
__device__ __forceinline__ void split2s(float2 a, float iv,
                                        uint32_t& hi, uint32_t& lo) {
    a.x *= iv; a.y *= iv;
    hi = pack_bf16x2(a.x, a.y);
    float hx = __uint_as_float(hi << 16);
    float hy = __uint_as_float(hi & 0xFFFF0000u);
    lo = pack_bf16x2(a.x - hx, a.y - hy);
}

// ---- packed bf16 hi/lo weights in B-fragment order (layout as R7/R8) ------
// KT16 = {5,5,5,4,4}, NT = {9,9,8,7,5}; per-layer floats = 3*KT*NT*128
__device__ float g_Wpad[68352];

__global__ void prep_weights(const float* W0, const float* W1, const float* W2,
                             const float* W3, const float* W4) {
    const int DIN[5]  = {74, 70, 65, 60, 55};
    const int DOUT[5] = {70, 65, 60, 55, 37};
    const int KT[5]   = {5, 5, 5, 4, 4};
    const int NT[5]   = {9, 9, 8, 7, 5};
    const int OFF[6]  = {0, 17280, 34560, 49920, 60672, 68352};
    const float* Ws[5] = {W0, W1, W2, W3, W4};

    for (int idx = blockIdx.x * blockDim.x + threadIdx.x; idx < 68352;
         idx += gridDim.x * blockDim.x) {
        int l = 0;
        while (idx >= OFF[l + 1]) l++;
        int rel    = idx - OFF[l];
        int block  = rel >> 7;
        int within = rel & 127;
        int lane = within >> 2;
        int j    = within & 3;          // 0:b0hi 1:b1hi 2:b0lo 3:b1lo
        int pnb  = KT[l] * NT[l];
        int p    = block / pnb;
        int r    = block - p * pnb;
        int kt   = r / NT[l];
        int nt   = r - kt * NT[l];
        int k0   = kt * 16 + (lane & 3) * 2 + ((j & 1) ? 8 : 0);
        int col  = nt * 8 + (lane >> 2);
        float w0 = 0.f, w1 = 0.f;
        if (col < DOUT[l]) {
            if (k0     < DIN[l]) w0 = Ws[l][(p * DIN[l] + k0) * DOUT[l] + col];
            if (k0 + 1 < DIN[l]) w1 = Ws[l][(p * DIN[l] + k0 + 1) * DOUT[l] + col];
        }
        uint32_t packed;
        uint32_t hi = 0;
        asm("cvt.rn.bf16x2.f32 %0, %1, %2;" : "=r"(hi) : "f"(w1), "f"(w0));
        if (j < 2) {
            packed = hi;
        } else {
            float hx = __uint_as_float(hi << 16);
            float hy = __uint_as_float(hi & 0xFFFF0000u);
            asm("cvt.rn.bf16x2.f32 %0, %1, %2;"
                : "=r"(packed) : "f"(w1 - hy), "f"(w0 - hx));
        }
        g_Wpad[idx] = __uint_as_float(packed);
    }
}

struct SmemLayout {
    float buf0[MROWS * ST];
    float buf1[MROWS * ST];
    float nA[128];     // n = deg^-1/2
    float n2[128];     // n^2 (=1/d)
    float invn[128];   // 1/n (=sqrt d)
    float red[128];
    float gate[128];
    int   rowptr[104];
    int   cnt[128];
    unsigned short csr[EDGES];
};

// ---- propagation (R8 style): out~[v] = n2[v] * sum_e in~[src_e] -----------
template <int DINP>
__device__ __forceinline__ void prop(const float* __restrict__ in,
                                     float* __restrict__ outb,
                                     const float* __restrict__ n2,
                                     const int* __restrict__ rowptr,
                                     const unsigned short* __restrict__ csr,
                                     int tid) {
    constexpr int NG = DINP / 8;
    for (int task = tid; task < NODES * NG; task += NTHR) {
        int v  = task / NG;
        int g  = task - v * NG;
        int c0 = g * 8;
        float4 a0 = make_float4(0.f, 0.f, 0.f, 0.f);
        float4 a1 = make_float4(0.f, 0.f, 0.f, 0.f);
        int e0 = rowptr[v], e1 = rowptr[v + 1];
        for (int e = e0; e < e1; e++) {
            int s = csr[e];
            const float4* r = reinterpret_cast<const float4*>(in + s * ST + c0);
            float4 r0 = r[0], r1 = r[1];
            a0.x += r0.x; a0.y += r0.y; a0.z += r0.z; a0.w += r0.w;
            a1.x += r1.x; a1.y += r1.y; a1.z += r1.z; a1.w += r1.w;
        }
        float f = n2[v];
        a0.x *= f; a0.y *= f; a0.z *= f; a0.w *= f;
        a1.x *= f; a1.y *= f; a1.z *= f; a1.w *= f;
        float4* o = reinterpret_cast<float4*>(outb + v * ST + c0);
        o[0] = a0; o[1] = a1;
    }
}

// ---- GEMM pass (3xBF16): one m-tile, all NT n-tiles; A scaled by invn -----
template <int KT, int NT>
__device__ __forceinline__ void gemm_mma(float (*C)[4],
                                         const float* __restrict__ H,
                                         const float* __restrict__ Wp,
                                         const float* __restrict__ invn,
                                         int wid, int lane) {
    int r0 = wid * 16 + (lane >> 2);
    float iv0 = invn[r0];
    float iv1 = invn[r0 + 8];
    const float* hb = H + r0 * ST + (lane & 3) * 2;
#pragma unroll
    for (int kt = 0; kt < KT; kt++) {
        const float* hm = hb + kt * 16;
        float2 p0 = *reinterpret_cast<const float2*>(hm);
        float2 p1 = *reinterpret_cast<const float2*>(hm + 8 * ST);
        float2 p2 = *reinterpret_cast<const float2*>(hm + 8);
        float2 p3 = *reinterpret_cast<const float2*>(hm + 8 + 8 * ST);
        uint32_t ahi[4], alo[4];
        split2s(p0, iv0, ahi[0], alo[0]);
        split2s(p1, iv1, ahi[1], alo[1]);
        split2s(p2, iv0, ahi[2], alo[2]);
        split2s(p3, iv1, ahi[3], alo[3]);
        const float4* wrow = reinterpret_cast<const float4*>(Wp) +
                             (size_t)kt * NT * 32 + lane;
#pragma unroll
        for (int nt = 0; nt < NT; nt++) {
            float4 w = __ldg(wrow + nt * 32);
            uint32_t bh0 = __float_as_uint(w.x);
            uint32_t bh1 = __float_as_uint(w.y);
            uint32_t bl0 = __float_as_uint(w.z);
            uint32_t bl1 = __float_as_uint(w.w);
            mma_bf16(C[nt], ahi, bh0, bh1);
            mma_bf16(C[nt], ahi, bl0, bl1);
            mma_bf16(C[nt], alo, bh0, bh1);
        }
    }
}

// ---- one TAGConv layer ----------------------------------------------------
// stores h~_out = n (.) relu(C + bias); zero-fills cols [ZLO, ZHI).
// GEMM + epilogue on warps 0-6 (7 m-tiles cover 112 >= 100 rows);
// warp 7 zero-fills pad cols concurrently with gemm_V/epilogue.
template <int KT, int NT, int DOUT, int ZLO, int ZHI>
__device__ __forceinline__ void layer(float* bufIn, float* bufOut,
                                      const float* __restrict__ Wp,
                                      const float* __restrict__ B,
                                      SmemLayout* sm, int tid) {
    constexpr int DINP = KT * 16;
    constexpr int PSZ  = KT * NT * 128;
    int wid  = tid >> 5;
    int lane = tid & 31;

    // U~ = n2 (.) A h~ -> bufOut (all 8 warps)
    prop<DINP>(bufIn, bufOut, sm->n2, sm->rowptr, sm->csr, tid);
    __syncthreads();

    float C[NT][4];
    if (wid < 7) {
#pragma unroll
        for (int nt = 0; nt < NT; nt++)
#pragma unroll
            for (int i = 0; i < 4; i++) C[nt][i] = 0.f;
        gemm_mma<KT, NT>(C, bufIn,  Wp,       sm->invn, wid, lane);  // h @ Wa
        gemm_mma<KT, NT>(C, bufOut, Wp + PSZ, sm->invn, wid, lane);  // U @ Wb
    }
    __syncthreads();

    // V~ -> bufIn (h dead; all 8 warps)
    prop<DINP>(bufOut, bufIn, sm->n2, sm->rowptr, sm->csr, tid);
    __syncthreads();

    if (wid < 7) {
        gemm_mma<KT, NT>(C, bufIn, Wp + 2 * PSZ, sm->invn, wid, lane); // V @ Wc

        // epilogue: bias + relu, scale by n[v] -> bufOut
        int r0 = wid * 16 + (lane >> 2);
        int cb = 2 * (lane & 3);
        float nv0 = (r0     < NODES) ? sm->nA[r0]     : 0.f;
        float nv1 = (r0 + 8 < NODES) ? sm->nA[r0 + 8] : 0.f;
#pragma unroll
        for (int nt = 0; nt < NT; nt++) {
            int c = nt * 8 + cb;
            float b0v = (c     < DOUT) ? __ldg(B + c)     : 0.f;
            float b1v = (c + 1 < DOUT) ? __ldg(B + c + 1) : 0.f;
            float v0 = (c     < DOUT) ? fmaxf(C[nt][0] + b0v, 0.f) * nv0 : 0.f;
            float v1 = (c + 1 < DOUT) ? fmaxf(C[nt][1] + b1v, 0.f) * nv0 : 0.f;
            if (r0 < NODES)
                *reinterpret_cast<float2*>(bufOut + r0 * ST + c) =
                    make_float2(v0, v1);
            float v2 = (c     < DOUT) ? fmaxf(C[nt][2] + b0v, 0.f) * nv1 : 0.f;
            float v3 = (c + 1 < DOUT) ? fmaxf(C[nt][3] + b1v, 0.f) * nv1 : 0.f;
            if (r0 + 8 < NODES)
                *reinterpret_cast<float2*>(bufOut + (r0 + 8) * ST + c) =
                    make_float2(v2, v3);
        }
    } else if (ZHI > ZLO) {
        // warp 7: zero pad cols [ZLO, ZHI) for rows < NODES (disjoint from
        // epilogue's data-column writes)
        constexpr int ZW = ZHI - ZLO;
        for (int idx = lane; idx < NODES * ZW; idx += 32) {
            int r = idx / ZW;
            int c = ZLO + (idx - r * ZW);
            bufOut[r * ST + c] = 0.f;
        }
    }
    __syncthreads();
}

__global__ void __launch_bounds__(NTHR, 2)
gnn_fused_kernel(const float* __restrict__ x,
                 const int* __restrict__ src,
                 const int* __restrict__ dst,
                 const float* __restrict__ b0, const float* __restrict__ b1,
                 const float* __restrict__ b2, const float* __restrict__ b3,
                 const float* __restrict__ b4,
                 const float* __restrict__ gw, const float* __restrict__ gb,
                 float* __restrict__ out) {
    extern __shared__ char smem_raw[];
    SmemLayout* sm = reinterpret_cast<SmemLayout*>(smem_raw);
    const int tid = threadIdx.x;
    const int g   = blockIdx.x;

    float* A = sm->buf0;
    float* B = sm->buf1;

    // ---- zero both feature buffers (pad invariant)
    {
        float4* z = reinterpret_cast<float4*>(sm->buf0);
        const int nq = 2 * MROWS * ST / 4;
        for (int i = tid; i < nq; i += NTHR)
            z[i] = make_float4(0.f, 0.f, 0.f, 0.f);
    }
    if (tid < 128) sm->cnt[tid] = 0;
    __syncthreads();

    // ---- degree count
    const int* srcg = src + g * EDGES;
    const int* dstg = dst + g * EDGES;
    const int base = g * NODES;
    for (int e = tid; e < EDGES; e += NTHR) {
        int dl = dstg[e] - base;
        atomicAdd(&sm->cnt[dl], 1);
    }
    __syncthreads();

    if (tid < 128) {
        float d = fmaxf((float)sm->cnt[tid], 1.f);
        sm->nA[tid]   = rsqrtf(d);
        sm->n2[tid]   = 1.0f / d;
        sm->invn[tid] = sqrtf(d);
    }
    for (int off = 1; off < 128; off <<= 1) {       // inclusive scan
        int t = 0;
        if (tid < 128 && tid >= off) t = sm->cnt[tid - off];
        __syncthreads();
        if (tid < 128 && tid >= off) sm->cnt[tid] += t;
        __syncthreads();
    }
    if (tid == 0) sm->rowptr[0] = 0;
    if (tid < NODES) sm->rowptr[tid + 1] = sm->cnt[tid];
    __syncthreads();
    if (tid < NODES) sm->cnt[tid] = sm->rowptr[tid];
    __syncthreads();
    for (int e = tid; e < EDGES; e += NTHR) {
        int sl = srcg[e] - base;
        int dl = dstg[e] - base;
        int pos = atomicAdd(&sm->cnt[dl], 1);
        sm->csr[pos] = (unsigned short)sl;
    }
    __syncthreads();

    // ---- load pre-scaled x~ = n (.) x
    {
        const float* xg = x + (size_t)g * (NODES * 74);
        for (int idx = tid; idx < NODES * 74; idx += NTHR) {
            int v = idx / 74;
            int c = idx - v * 74;
            A[v * ST + c] = xg[idx] * sm->nA[v];
        }
    }
    __syncthreads();

    // ---- 5 TAGConv layers    KT NT DOUT ZLO ZHI       Wpad offset
    layer<5, 9, 70, 72, 80>(A, B, g_Wpad +     0, b0, sm, tid);
    layer<5, 9, 65, 72, 80>(B, A, g_Wpad + 17280, b1, sm, tid);
    layer<5, 8, 60, 64, 64>(A, B, g_Wpad + 34560, b2, sm, tid);
    layer<4, 7, 55, 56, 64>(B, A, g_Wpad + 49920, b3, sm, tid);
    layer<4, 5, 37, 40, 40>(A, B, g_Wpad + 60672, b4, sm, tid);
    float* H = B;   // final h~ = n (.) h : 100 x 37 (cols 37..39 zero)

    // ---- gate = invn * (h~ @ gw) + gb ; softmax; pool
    float gval = -1e30f;
    if (tid < NODES) {
        float s = 0.f;
#pragma unroll
        for (int c = 0; c < 37; c++)
            s += H[tid * ST + c] * __ldg(gw + c);
        s = s * sm->invn[tid] + __ldg(gb);
        sm->gate[tid] = s;
        gval = s;
    }
    if (tid < 128) sm->red[tid] = gval;
    __syncthreads();
    for (int s = 64; s > 0; s >>= 1) {
        if (tid < s) sm->red[tid] = fmaxf(sm->red[tid], sm->red[tid + s]);
        __syncthreads();
    }
    float gmax = sm->red[0];
    __syncthreads();

    float ev = 0.f;
    if (tid < NODES) {
        ev = expf(sm->gate[tid] - gmax);
        sm->gate[tid] = ev * sm->invn[tid];   // fold invn for pooled h~ sum
    }
    if (tid < 128) sm->red[tid] = ev;
    __syncthreads();
    for (int s = 64; s > 0; s >>= 1) {
        if (tid < s) sm->red[tid] += sm->red[tid + s];
        __syncthreads();
    }
    float Z = sm->red[0];

    if (tid < 37) {
        float a = 0.f;
        for (int v = 0; v < NODES; v++)
            a += sm->gate[v] * H[v * ST + tid];
        out[g * 37 + tid] = a / Z;
    }
}

extern "C" void kernel_launch(void* const* d_in, const int* in_sizes, int n_in,
                              void* d_out, int out_size) {
    const float* x   = (const float*)d_in[0];
    const int*   src = (const int*)d_in[1];
    const int*   dst = (const int*)d_in[2];
    const float* W0 = (const float*)d_in[4];
    const float* b0 = (const float*)d_in[5];
    const float* W1 = (const float*)d_in[6];
    const float* b1 = (const float*)d_in[7];
    const float* W2 = (const float*)d_in[8];
    const float* b2 = (const float*)d_in[9];
    const float* W3 = (const float*)d_in[10];
    const float* b3 = (const float*)d_in[11];
    const float* W4 = (const float*)d_in[12];
    const float* b4 = (const float*)d_in[13];
    const float* gw = (const float*)d_in[14];
    const float* gb = (const float*)d_in[15];
    float* out = (float*)d_out;

    prep_weights<<<128, 256>>>(W0, W1, W2, W3, W4);

    const int smem_bytes = (int)sizeof(SmemLayout);
    cudaFuncSetAttribute(gnn_fused_kernel,
                         cudaFuncAttributeMaxDynamicSharedMemorySize,
                         smem_bytes);
    gnn_fused_kernel<<<5000, NTHR, smem_bytes>>>(
        x, src, dst,
        b0, b1, b2, b3, b4,
        gw, gb, out);
}

// round 13
// speedup vs baseline: 1.3685x; 1.0201x over previous
#include <cuda_runtime.h>
#include <cuda_bf16.h>
#include <math.h>
#include <stdint.h>

// ---------------------------------------------------------------------------
// Fused per-graph GNN: 5x TAGConv(K=2) + ReLU + gated softmax pooling.
// One CTA per graph (5000 CTAs, 256 threads). All features in shared memory.
//
// R13 = R12 + degree-sorted prop scheduling:
//   - prop tasks visit nodes in degree-sorted order (32-bin counting sort),
//     so the ~4 nodes sharing a warp have near-equal degree and the
//     max-degree divergence waste (~75% extra masked iterations) vanishes.
//   - everything else identical to R12 (7 m-tiles, 3xBF16 m16n8k16,
//     pre-scaled h~, warp 7 pad-fill overlap).
// ---------------------------------------------------------------------------

#define NODES   100
#define EDGES   400
#define NTHR    256
#define ST      84      // smem row stride (floats); 84 mod 32 = 20 -> conflict-free
#define MROWS   112     // 7 m-tiles * 16

__device__ __forceinline__ uint32_t pack_bf16x2(float lo, float hi) {
    uint32_t r;
    asm("cvt.rn.bf16x2.f32 %0, %1, %2;" : "=r"(r) : "f"(hi), "f"(lo));
    return r;
}

__device__ __forceinline__ void mma_bf16(float c[4], const uint32_t a[4],
                                         uint32_t b0, uint32_t b1) {
    asm("mma.sync.aligned.m16n8k16.row.col.f32.bf16.bf16.f32 "
        "{%0,%1,%2,%3}, {%4,%5,%6,%7}, {%8,%9}, {%0,%1,%2,%3};"
        : "+f"(c[0]), "+f"(c[1]), "+f"(c[2]), "+f"(c[3])
        : "r"(a[0]), "r"(a[1]), "r"(a[2]), "r"(a[3]), "r"(b0), "r"(b1));
}

// scale by iv then hi/lo split into two bf16x2 regs
__device__ __forceinline__ void split2s(float2 a, float iv,
                                        uint32_t& hi, uint32_t& lo) {
    a.x *= iv; a.y *= iv;
    hi = pack_bf16x2(a.x, a.y);
    float hx = __uint_as_float(hi << 16);
    float hy = __uint_as_float(hi & 0xFFFF0000u);
    lo = pack_bf16x2(a.x - hx, a.y - hy);
}

// ---- packed bf16 hi/lo weights in B-fragment order (layout as R7/R8) ------
// KT16 = {5,5,5,4,4}, NT = {9,9,8,7,5}; per-layer floats = 3*KT*NT*128
__device__ float g_Wpad[68352];

__global__ void prep_weights(const float* W0, const float* W1, const float* W2,
                             const float* W3, const float* W4) {
    const int DIN[5]  = {74, 70, 65, 60, 55};
    const int DOUT[5] = {70, 65, 60, 55, 37};
    const int KT[5]   = {5, 5, 5, 4, 4};
    const int NT[5]   = {9, 9, 8, 7, 5};
    const int OFF[6]  = {0, 17280, 34560, 49920, 60672, 68352};
    const float* Ws[5] = {W0, W1, W2, W3, W4};

    for (int idx = blockIdx.x * blockDim.x + threadIdx.x; idx < 68352;
         idx += gridDim.x * blockDim.x) {
        int l = 0;
        while (idx >= OFF[l + 1]) l++;
        int rel    = idx - OFF[l];
        int block  = rel >> 7;
        int within = rel & 127;
        int lane = within >> 2;
        int j    = within & 3;          // 0:b0hi 1:b1hi 2:b0lo 3:b1lo
        int pnb  = KT[l] * NT[l];
        int p    = block / pnb;
        int r    = block - p * pnb;
        int kt   = r / NT[l];
        int nt   = r - kt * NT[l];
        int k0   = kt * 16 + (lane & 3) * 2 + ((j & 1) ? 8 : 0);
        int col  = nt * 8 + (lane >> 2);
        float w0 = 0.f, w1 = 0.f;
        if (col < DOUT[l]) {
            if (k0     < DIN[l]) w0 = Ws[l][(p * DIN[l] + k0) * DOUT[l] + col];
            if (k0 + 1 < DIN[l]) w1 = Ws[l][(p * DIN[l] + k0 + 1) * DOUT[l] + col];
        }
        uint32_t packed;
        uint32_t hi = 0;
        asm("cvt.rn.bf16x2.f32 %0, %1, %2;" : "=r"(hi) : "f"(w1), "f"(w0));
        if (j < 2) {
            packed = hi;
        } else {
            float hx = __uint_as_float(hi << 16);
            float hy = __uint_as_float(hi & 0xFFFF0000u);
            asm("cvt.rn.bf16x2.f32 %0, %1, %2;"
                : "=r"(packed) : "f"(w1 - hy), "f"(w0 - hx));
        }
        g_Wpad[idx] = __uint_as_float(packed);
    }
}

struct SmemLayout {
    float buf0[MROWS * ST];
    float buf1[MROWS * ST];
    float nA[128];     // n = deg^-1/2
    float n2[128];     // n^2 (=1/d)
    float invn[128];   // 1/n (=sqrt d)
    float red[128];
    float gate[128];
    int   rowptr[104];
    int   cnt[128];
    int   ord[128];    // nodes in degree-sorted order (prop task mapping)
    int   dhist[32];   // degree histogram / offsets for counting sort
    unsigned short csr[EDGES];
};

// ---- propagation: out~[ord[i]] = n2 * sum_e in~[src_e], degree-sorted -----
template <int DINP>
__device__ __forceinline__ void prop(const float* __restrict__ in,
                                     float* __restrict__ outb,
                                     const float* __restrict__ n2,
                                     const int* __restrict__ rowptr,
                                     const unsigned short* __restrict__ csr,
                                     const int* __restrict__ ord,
                                     int tid) {
    constexpr int NG = DINP / 8;
    for (int task = tid; task < NODES * NG; task += NTHR) {
        int vi = task / NG;
        int g  = task - vi * NG;
        int v  = ord[vi];               // degree-sorted node
        int c0 = g * 8;
        float4 a0 = make_float4(0.f, 0.f, 0.f, 0.f);
        float4 a1 = make_float4(0.f, 0.f, 0.f, 0.f);
        int e0 = rowptr[v], e1 = rowptr[v + 1];
        for (int e = e0; e < e1; e++) {
            int s = csr[e];
            const float4* r = reinterpret_cast<const float4*>(in + s * ST + c0);
            float4 r0 = r[0], r1 = r[1];
            a0.x += r0.x; a0.y += r0.y; a0.z += r0.z; a0.w += r0.w;
            a1.x += r1.x; a1.y += r1.y; a1.z += r1.z; a1.w += r1.w;
        }
        float f = n2[v];
        a0.x *= f; a0.y *= f; a0.z *= f; a0.w *= f;
        a1.x *= f; a1.y *= f; a1.z *= f; a1.w *= f;
        float4* o = reinterpret_cast<float4*>(outb + v * ST + c0);
        o[0] = a0; o[1] = a1;
    }
}

// ---- GEMM pass (3xBF16): one m-tile, all NT n-tiles; A scaled by invn -----
template <int KT, int NT>
__device__ __forceinline__ void gemm_mma(float (*C)[4],
                                         const float* __restrict__ H,
                                         const float* __restrict__ Wp,
                                         const float* __restrict__ invn,
                                         int wid, int lane) {
    int r0 = wid * 16 + (lane >> 2);
    float iv0 = invn[r0];
    float iv1 = invn[r0 + 8];
    const float* hb = H + r0 * ST + (lane & 3) * 2;
#pragma unroll
    for (int kt = 0; kt < KT; kt++) {
        const float* hm = hb + kt * 16;
        float2 p0 = *reinterpret_cast<const float2*>(hm);
        float2 p1 = *reinterpret_cast<const float2*>(hm + 8 * ST);
        float2 p2 = *reinterpret_cast<const float2*>(hm + 8);
        float2 p3 = *reinterpret_cast<const float2*>(hm + 8 + 8 * ST);
        uint32_t ahi[4], alo[4];
        split2s(p0, iv0, ahi[0], alo[0]);
        split2s(p1, iv1, ahi[1], alo[1]);
        split2s(p2, iv0, ahi[2], alo[2]);
        split2s(p3, iv1, ahi[3], alo[3]);
        const float4* wrow = reinterpret_cast<const float4*>(Wp) +
                             (size_t)kt * NT * 32 + lane;
#pragma unroll
        for (int nt = 0; nt < NT; nt++) {
            float4 w = __ldg(wrow + nt * 32);
            uint32_t bh0 = __float_as_uint(w.x);
            uint32_t bh1 = __float_as_uint(w.y);
            uint32_t bl0 = __float_as_uint(w.z);
            uint32_t bl1 = __float_as_uint(w.w);
            mma_bf16(C[nt], ahi, bh0, bh1);
            mma_bf16(C[nt], ahi, bl0, bl1);
            mma_bf16(C[nt], alo, bh0, bh1);
        }
    }
}

// ---- one TAGConv layer ----------------------------------------------------
// stores h~_out = n (.) relu(C + bias); zero-fills cols [ZLO, ZHI).
// GEMM + epilogue on warps 0-6 (7 m-tiles cover 112 >= 100 rows);
// warp 7 zero-fills pad cols concurrently with gemm_V/epilogue.
template <int KT, int NT, int DOUT, int ZLO, int ZHI>
__device__ __forceinline__ void layer(float* bufIn, float* bufOut,
                                      const float* __restrict__ Wp,
                                      const float* __restrict__ B,
                                      SmemLayout* sm, int tid) {
    constexpr int DINP = KT * 16;
    constexpr int PSZ  = KT * NT * 128;
    int wid  = tid >> 5;
    int lane = tid & 31;

    // U~ = n2 (.) A h~ -> bufOut (all 8 warps)
    prop<DINP>(bufIn, bufOut, sm->n2, sm->rowptr, sm->csr, sm->ord, tid);
    __syncthreads();

    float C[NT][4];
    if (wid < 7) {
#pragma unroll
        for (int nt = 0; nt < NT; nt++)
#pragma unroll
            for (int i = 0; i < 4; i++) C[nt][i] = 0.f;
        gemm_mma<KT, NT>(C, bufIn,  Wp,       sm->invn, wid, lane);  // h @ Wa
        gemm_mma<KT, NT>(C, bufOut, Wp + PSZ, sm->invn, wid, lane);  // U @ Wb
    }
    __syncthreads();

    // V~ -> bufIn (h dead; all 8 warps)
    prop<DINP>(bufOut, bufIn, sm->n2, sm->rowptr, sm->csr, sm->ord, tid);
    __syncthreads();

    if (wid < 7) {
        gemm_mma<KT, NT>(C, bufIn, Wp + 2 * PSZ, sm->invn, wid, lane); // V @ Wc

        // epilogue: bias + relu, scale by n[v] -> bufOut
        int r0 = wid * 16 + (lane >> 2);
        int cb = 2 * (lane & 3);
        float nv0 = (r0     < NODES) ? sm->nA[r0]     : 0.f;
        float nv1 = (r0 + 8 < NODES) ? sm->nA[r0 + 8] : 0.f;
#pragma unroll
        for (int nt = 0; nt < NT; nt++) {
            int c = nt * 8 + cb;
            float b0v = (c     < DOUT) ? __ldg(B + c)     : 0.f;
            float b1v = (c + 1 < DOUT) ? __ldg(B + c + 1) : 0.f;
            float v0 = (c     < DOUT) ? fmaxf(C[nt][0] + b0v, 0.f) * nv0 : 0.f;
            float v1 = (c + 1 < DOUT) ? fmaxf(C[nt][1] + b1v, 0.f) * nv0 : 0.f;
            if (r0 < NODES)
                *reinterpret_cast<float2*>(bufOut + r0 * ST + c) =
                    make_float2(v0, v1);
            float v2 = (c     < DOUT) ? fmaxf(C[nt][2] + b0v, 0.f) * nv1 : 0.f;
            float v3 = (c + 1 < DOUT) ? fmaxf(C[nt][3] + b1v, 0.f) * nv1 : 0.f;
            if (r0 + 8 < NODES)
                *reinterpret_cast<float2*>(bufOut + (r0 + 8) * ST + c) =
                    make_float2(v2, v3);
        }
    } else if (ZHI > ZLO) {
        // warp 7: zero pad cols [ZLO, ZHI) for rows < NODES (disjoint from
        // epilogue's data-column writes)
        constexpr int ZW = ZHI - ZLO;
        for (int idx = lane; idx < NODES * ZW; idx += 32) {
            int r = idx / ZW;
            int c = ZLO + (idx - r * ZW);
            bufOut[r * ST + c] = 0.f;
        }
    }
    __syncthreads();
}

__global__ void __launch_bounds__(NTHR, 2)
gnn_fused_kernel(const float* __restrict__ x,
                 const int* __restrict__ src,
                 const int* __restrict__ dst,
                 const float* __restrict__ b0, const float* __restrict__ b1,
                 const float* __restrict__ b2, const float* __restrict__ b3,
                 const float* __restrict__ b4,
                 const float* __restrict__ gw, const float* __restrict__ gb,
                 float* __restrict__ out) {
    extern __shared__ char smem_raw[];
    SmemLayout* sm = reinterpret_cast<SmemLayout*>(smem_raw);
    const int tid = threadIdx.x;
    const int g   = blockIdx.x;

    float* A = sm->buf0;
    float* B = sm->buf1;

    // ---- zero both feature buffers (pad invariant)
    {
        float4* z = reinterpret_cast<float4*>(sm->buf0);
        const int nq = 2 * MROWS * ST / 4;
        for (int i = tid; i < nq; i += NTHR)
            z[i] = make_float4(0.f, 0.f, 0.f, 0.f);
    }
    if (tid < 128) sm->cnt[tid] = 0;
    if (tid < 32)  sm->dhist[tid] = 0;
    __syncthreads();

    // ---- degree count
    const int* srcg = src + g * EDGES;
    const int* dstg = dst + g * EDGES;
    const int base = g * NODES;
    for (int e = tid; e < EDGES; e += NTHR) {
        int dl = dstg[e] - base;
        atomicAdd(&sm->cnt[dl], 1);
    }
    __syncthreads();

    int mydeg = 0;
    if (tid < 128) {
        mydeg = sm->cnt[tid];
        float d = fmaxf((float)mydeg, 1.f);
        sm->nA[tid]   = rsqrtf(d);
        sm->n2[tid]   = 1.0f / d;
        sm->invn[tid] = sqrtf(d);
    }
    // degree histogram (cnt still holds degrees)
    if (tid < NODES)
        atomicAdd(&sm->dhist[mydeg < 31 ? mydeg : 31], 1);
    __syncthreads();
    if (tid == 0) {            // exclusive scan of 32 bins
        int acc = 0;
#pragma unroll
        for (int i = 0; i < 32; i++) {
            int t = sm->dhist[i];
            sm->dhist[i] = acc;
            acc += t;
        }
    }
    __syncthreads();
    if (tid < NODES) {         // counting-sort placement
        int p = atomicAdd(&sm->dhist[mydeg < 31 ? mydeg : 31], 1);
        sm->ord[p] = tid;
    }
    // inclusive scan over cnt -> rowptr
    for (int off = 1; off < 128; off <<= 1) {
        int t = 0;
        if (tid < 128 && tid >= off) t = sm->cnt[tid - off];
        __syncthreads();
        if (tid < 128 && tid >= off) sm->cnt[tid] += t;
        __syncthreads();
    }
    if (tid == 0) sm->rowptr[0] = 0;
    if (tid < NODES) sm->rowptr[tid + 1] = sm->cnt[tid];
    __syncthreads();
    if (tid < NODES) sm->cnt[tid] = sm->rowptr[tid];
    __syncthreads();
    for (int e = tid; e < EDGES; e += NTHR) {
        int sl = srcg[e] - base;
        int dl = dstg[e] - base;
        int pos = atomicAdd(&sm->cnt[dl], 1);
        sm->csr[pos] = (unsigned short)sl;
    }
    __syncthreads();

    // ---- load pre-scaled x~ = n (.) x
    {
        const float* xg = x + (size_t)g * (NODES * 74);
        for (int idx = tid; idx < NODES * 74; idx += NTHR) {
            int v = idx / 74;
            int c = idx - v * 74;
            A[v * ST + c] = xg[idx] * sm->nA[v];
        }
    }
    __syncthreads();

    // ---- 5 TAGConv layers    KT NT DOUT ZLO ZHI       Wpad offset
    layer<5, 9, 70, 72, 80>(A, B, g_Wpad +     0, b0, sm, tid);
    layer<5, 9, 65, 72, 80>(B, A, g_Wpad + 17280, b1, sm, tid);
    layer<5, 8, 60, 64, 64>(A, B, g_Wpad + 34560, b2, sm, tid);
    layer<4, 7, 55, 56, 64>(B, A, g_Wpad + 49920, b3, sm, tid);
    layer<4, 5, 37, 40, 40>(A, B, g_Wpad + 60672, b4, sm, tid);
    float* H = B;   // final h~ = n (.) h : 100 x 37 (cols 37..39 zero)

    // ---- gate = invn * (h~ @ gw) + gb ; softmax; pool
    float gval = -1e30f;
    if (tid < NODES) {
        float s = 0.f;
#pragma unroll
        for (int c = 0; c < 37; c++)
            s += H[tid * ST + c] * __ldg(gw + c);
        s = s * sm->invn[tid] + __ldg(gb);
        sm->gate[tid] = s;
        gval = s;
    }
    if (tid < 128) sm->red[tid] = gval;
    __syncthreads();
    for (int s = 64; s > 0; s >>= 1) {
        if (tid < s) sm->red[tid] = fmaxf(sm->red[tid], sm->red[tid + s]);
        __syncthreads();
    }
    float gmax = sm->red[0];
    __syncthreads();

    float ev = 0.f;
    if (tid < NODES) {
        ev = expf(sm->gate[tid] - gmax);
        sm->gate[tid] = ev * sm->invn[tid];   // fold invn for pooled h~ sum
    }
    if (tid < 128) sm->red[tid] = ev;
    __syncthreads();
    for (int s = 64; s > 0; s >>= 1) {
        if (tid < s) sm->red[tid] += sm->red[tid + s];
        __syncthreads();
    }
    float Z = sm->red[0];

    if (tid < 37) {
        float a = 0.f;
        for (int v = 0; v < NODES; v++)
            a += sm->gate[v] * H[v * ST + tid];
        out[g * 37 + tid] = a / Z;
    }
}

extern "C" void kernel_launch(void* const* d_in, const int* in_sizes, int n_in,
                              void* d_out, int out_size) {
    const float* x   = (const float*)d_in[0];
    const int*   src = (const int*)d_in[1];
    const int*   dst = (const int*)d_in[2];
    const float* W0 = (const float*)d_in[4];
    const float* b0 = (const float*)d_in[5];
    const float* W1 = (const float*)d_in[6];
    const float* b1 = (const float*)d_in[7];
    const float* W2 = (const float*)d_in[8];
    const float* b2 = (const float*)d_in[9];
    const float* W3 = (const float*)d_in[10];
    const float* b3 = (const float*)d_in[11];
    const float* W4 = (const float*)d_in[12];
    const float* b4 = (const float*)d_in[13];
    const float* gw = (const float*)d_in[14];
    const float* gb = (const float*)d_in[15];
    float* out = (float*)d_out;

    prep_weights<<<128, 256>>>(W0, W1, W2, W3, W4);

    const int smem_bytes = (int)sizeof(SmemLayout);
    cudaFuncSetAttribute(gnn_fused_kernel,
                         cudaFuncAttributeMaxDynamicSharedMemorySize,
                         smem_bytes);
    gnn_fused_kernel<<<5000, NTHR, smem_bytes>>>(
        x, src, dst,
        b0, b1, b2, b3, b4,
        gw, gb, out);
}

// round 15
// speedup vs baseline: 1.3818x; 1.0097x over previous
#include <cuda_runtime.h>
#include <cuda_bf16.h>
#include <math.h>
#include <stdint.h>

// ---------------------------------------------------------------------------
// Fused per-graph GNN: 5x TAGConv(K=2) + ReLU + gated softmax pooling.
// One CTA per graph (5000 CTAs, 256 threads). All features in shared memory.
//
// R15 = R13 minus wasted L1 traffic (tcgen05 is toolchain-blocked):
//   - no full buffer zero-init (only x pad cols 74..79 zeroed): GEMM reads of
//     uninitialized rows 100-111 only affect discarded C rows; stale columns
//     beyond each layer's true DIN hit ZERO rows of the padded weight image.
//   - no per-layer pad zero-fill loops (same reason).
//   - prop width = ceil(DIN_in/8)*8 per layer (72/72/56 instead of 80/80/64
//     for L1/L2/L4), cutting gather traffic ~7%.
//   - engine unchanged: 3xBF16 m16n8k16, 7 m-tile warps, degree-sorted prop,
//     pre-scaled h~ = n (.) h.
// ---------------------------------------------------------------------------

#define NODES   100
#define EDGES   400
#define NTHR    256
#define ST      84      // smem row stride (floats); 84 mod 32 = 20 -> conflict-free
#define MROWS   112     // 7 m-tiles * 16

__device__ __forceinline__ uint32_t pack_bf16x2(float lo, float hi) {
    uint32_t r;
    asm("cvt.rn.bf16x2.f32 %0, %1, %2;" : "=r"(r) : "f"(hi), "f"(lo));
    return r;
}

__device__ __forceinline__ void mma_bf16(float c[4], const uint32_t a[4],
                                         uint32_t b0, uint32_t b1) {
    asm("mma.sync.aligned.m16n8k16.row.col.f32.bf16.bf16.f32 "
        "{%0,%1,%2,%3}, {%4,%5,%6,%7}, {%8,%9}, {%0,%1,%2,%3};"
        : "+f"(c[0]), "+f"(c[1]), "+f"(c[2]), "+f"(c[3])
        : "r"(a[0]), "r"(a[1]), "r"(a[2]), "r"(a[3]), "r"(b0), "r"(b1));
}

// scale by iv then hi/lo split into two bf16x2 regs
__device__ __forceinline__ void split2s(float2 a, float iv,
                                        uint32_t& hi, uint32_t& lo) {
    a.x *= iv; a.y *= iv;
    hi = pack_bf16x2(a.x, a.y);
    float hx = __uint_as_float(hi << 16);
    float hy = __uint_as_float(hi & 0xFFFF0000u);
    lo = pack_bf16x2(a.x - hx, a.y - hy);
}

// ---- packed bf16 hi/lo weights in B-fragment order (layout as R7..R13) ----
// KT16 = {5,5,5,4,4}, NT = {9,9,8,7,5}; per-layer floats = 3*KT*NT*128
// Rows k >= DIN and cols >= DOUT are ZERO (this is what makes stale
// activation columns harmless).
__device__ float g_Wpad[68352];

__global__ void prep_weights(const float* W0, const float* W1, const float* W2,
                             const float* W3, const float* W4) {
    const int DIN[5]  = {74, 70, 65, 60, 55};
    const int DOUT[5] = {70, 65, 60, 55, 37};
    const int KT[5]   = {5, 5, 5, 4, 4};
    const int NT[5]   = {9, 9, 8, 7, 5};
    const int OFF[6]  = {0, 17280, 34560, 49920, 60672, 68352};
    const float* Ws[5] = {W0, W1, W2, W3, W4};

    for (int idx = blockIdx.x * blockDim.x + threadIdx.x; idx < 68352;
         idx += gridDim.x * blockDim.x) {
        int l = 0;
        while (idx >= OFF[l + 1]) l++;
        int rel    = idx - OFF[l];
        int block  = rel >> 7;
        int within = rel & 127;
        int lane = within >> 2;
        int j    = within & 3;          // 0:b0hi 1:b1hi 2:b0lo 3:b1lo
        int pnb  = KT[l] * NT[l];
        int p    = block / pnb;
        int r    = block - p * pnb;
        int kt   = r / NT[l];
        int nt   = r - kt * NT[l];
        int k0   = kt * 16 + (lane & 3) * 2 + ((j & 1) ? 8 : 0);
        int col  = nt * 8 + (lane >> 2);
        float w0 = 0.f, w1 = 0.f;
        if (col < DOUT[l]) {
            if (k0     < DIN[l]) w0 = Ws[l][(p * DIN[l] + k0) * DOUT[l] + col];
            if (k0 + 1 < DIN[l]) w1 = Ws[l][(p * DIN[l] + k0 + 1) * DOUT[l] + col];
        }
        uint32_t packed;
        uint32_t hi = 0;
        asm("cvt.rn.bf16x2.f32 %0, %1, %2;" : "=r"(hi) : "f"(w1), "f"(w0));
        if (j < 2) {
            packed = hi;
        } else {
            float hx = __uint_as_float(hi << 16);
            float hy = __uint_as_float(hi & 0xFFFF0000u);
            asm("cvt.rn.bf16x2.f32 %0, %1, %2;"
                : "=r"(packed) : "f"(w1 - hy), "f"(w0 - hx));
        }
        g_Wpad[idx] = __uint_as_float(packed);
    }
}

struct SmemLayout {
    float buf0[MROWS * ST];
    float buf1[MROWS * ST];
    float nA[128];     // n = deg^-1/2
    float n2[128];     // n^2 (=1/d)
    float invn[128];   // 1/n (=sqrt d)
    float red[128];
    float gate[128];
    int   rowptr[104];
    int   cnt[128];
    int   ord[128];    // nodes in degree-sorted order (prop task mapping)
    int   dhist[32];   // degree histogram / offsets for counting sort
    unsigned short csr[EDGES];
};

// ---- propagation over PW cols: out~[ord[i]] = n2 * sum_e in~[src_e] -------
template <int PW>
__device__ __forceinline__ void prop(const float* __restrict__ in,
                                     float* __restrict__ outb,
                                     const float* __restrict__ n2,
                                     const int* __restrict__ rowptr,
                                     const unsigned short* __restrict__ csr,
                                     const int* __restrict__ ord,
                                     int tid) {
    constexpr int NG = PW / 8;
    for (int task = tid; task < NODES * NG; task += NTHR) {
        int vi = task / NG;
        int g  = task - vi * NG;
        int v  = ord[vi];               // degree-sorted node
        int c0 = g * 8;
        float4 a0 = make_float4(0.f, 0.f, 0.f, 0.f);
        float4 a1 = make_float4(0.f, 0.f, 0.f, 0.f);
        int e0 = rowptr[v], e1 = rowptr[v + 1];
        for (int e = e0; e < e1; e++) {
            int s = csr[e];
            const float4* r = reinterpret_cast<const float4*>(in + s * ST + c0);
            float4 r0 = r[0], r1 = r[1];
            a0.x += r0.x; a0.y += r0.y; a0.z += r0.z; a0.w += r0.w;
            a1.x += r1.x; a1.y += r1.y; a1.z += r1.z; a1.w += r1.w;
        }
        float f = n2[v];
        a0.x *= f; a0.y *= f; a0.z *= f; a0.w *= f;
        a1.x *= f; a1.y *= f; a1.z *= f; a1.w *= f;
        float4* o = reinterpret_cast<float4*>(outb + v * ST + c0);
        o[0] = a0; o[1] = a1;
    }
}

// ---- GEMM pass (3xBF16): one m-tile, all NT n-tiles; A scaled by invn -----
template <int KT, int NT>
__device__ __forceinline__ void gemm_mma(float (*C)[4],
                                         const float* __restrict__ H,
                                         const float* __restrict__ Wp,
                                         const float* __restrict__ invn,
                                         int wid, int lane) {
    int r0 = wid * 16 + (lane >> 2);
    float iv0 = invn[r0];
    float iv1 = invn[r0 + 8];
    const float* hb = H + r0 * ST + (lane & 3) * 2;
#pragma unroll
    for (int kt = 0; kt < KT; kt++) {
        const float* hm = hb + kt * 16;
        float2 p0 = *reinterpret_cast<const float2*>(hm);
        float2 p1 = *reinterpret_cast<const float2*>(hm + 8 * ST);
        float2 p2 = *reinterpret_cast<const float2*>(hm + 8);
        float2 p3 = *reinterpret_cast<const float2*>(hm + 8 + 8 * ST);
        uint32_t ahi[4], alo[4];
        split2s(p0, iv0, ahi[0], alo[0]);
        split2s(p1, iv1, ahi[1], alo[1]);
        split2s(p2, iv0, ahi[2], alo[2]);
        split2s(p3, iv1, ahi[3], alo[3]);
        const float4* wrow = reinterpret_cast<const float4*>(Wp) +
                             (size_t)kt * NT * 32 + lane;
#pragma unroll
        for (int nt = 0; nt < NT; nt++) {
            float4 w = __ldg(wrow + nt * 32);
            uint32_t bh0 = __float_as_uint(w.x);
            uint32_t bh1 = __float_as_uint(w.y);
            uint32_t bl0 = __float_as_uint(w.z);
            uint32_t bl1 = __float_as_uint(w.w);
            mma_bf16(C[nt], ahi, bh0, bh1);
            mma_bf16(C[nt], ahi, bl0, bl1);
            mma_bf16(C[nt], alo, bh0, bh1);
        }
    }
}

// ---- one TAGConv layer ----------------------------------------------------
// PW = prop width (mult of 8, >= DIN of this layer's input).
// GEMM + epilogue on warps 0-6; no pad-fill needed anywhere (zero weights
// null out stale columns; garbage rows >= 100 only reach discarded C rows).
template <int PW, int KT, int NT, int DOUT>
__device__ __forceinline__ void layer(float* bufIn, float* bufOut,
                                      const float* __restrict__ Wp,
                                      const float* __restrict__ B,
                                      SmemLayout* sm, int tid) {
    constexpr int PSZ = KT * NT * 128;
    int wid  = tid >> 5;
    int lane = tid & 31;

    // U~ = n2 (.) A h~ -> bufOut (all 8 warps)
    prop<PW>(bufIn, bufOut, sm->n2, sm->rowptr, sm->csr, sm->ord, tid);
    __syncthreads();

    float C[NT][4];
    if (wid < 7) {
#pragma unroll
        for (int nt = 0; nt < NT; nt++)
#pragma unroll
            for (int i = 0; i < 4; i++) C[nt][i] = 0.f;
        gemm_mma<KT, NT>(C, bufIn,  Wp,       sm->invn, wid, lane);  // h @ Wa
        gemm_mma<KT, NT>(C, bufOut, Wp + PSZ, sm->invn, wid, lane);  // U @ Wb
    }
    __syncthreads();

    // V~ -> bufIn (h dead; all 8 warps)
    prop<PW>(bufOut, bufIn, sm->n2, sm->rowptr, sm->csr, sm->ord, tid);
    __syncthreads();

    if (wid < 7) {
        gemm_mma<KT, NT>(C, bufIn, Wp + 2 * PSZ, sm->invn, wid, lane); // V @ Wc

        // epilogue: bias + relu, scale by n[v] -> bufOut (cols 0..NT*8)
        int r0 = wid * 16 + (lane >> 2);
        int cb = 2 * (lane & 3);
        float nv0 = (r0     < NODES) ? sm->nA[r0]     : 0.f;
        float nv1 = (r0 + 8 < NODES) ? sm->nA[r0 + 8] : 0.f;
#pragma unroll
        for (int nt = 0; nt < NT; nt++) {
            int c = nt * 8 + cb;
            float b0v = (c     < DOUT) ? __ldg(B + c)     : 0.f;
            float b1v = (c + 1 < DOUT) ? __ldg(B + c + 1) : 0.f;
            float v0 = (c     < DOUT) ? fmaxf(C[nt][0] + b0v, 0.f) * nv0 : 0.f;
            float v1 = (c + 1 < DOUT) ? fmaxf(C[nt][1] + b1v, 0.f) * nv0 : 0.f;
            if (r0 < NODES)
                *reinterpret_cast<float2*>(bufOut + r0 * ST + c) =
                    make_float2(v0, v1);
            float v2 = (c     < DOUT) ? fmaxf(C[nt][2] + b0v, 0.f) * nv1 : 0.f;
            float v3 = (c + 1 < DOUT) ? fmaxf(C[nt][3] + b1v, 0.f) * nv1 : 0.f;
            if (r0 + 8 < NODES)
                *reinterpret_cast<float2*>(bufOut + (r0 + 8) * ST + c) =
                    make_float2(v2, v3);
        }
    }
    __syncthreads();
}

__global__ void __launch_bounds__(NTHR, 2)
gnn_fused_kernel(const float* __restrict__ x,
                 const int* __restrict__ src,
                 const int* __restrict__ dst,
                 const float* __restrict__ b0, const float* __restrict__ b1,
                 const float* __restrict__ b2, const float* __restrict__ b3,
                 const float* __restrict__ b4,
                 const float* __restrict__ gw, const float* __restrict__ gb,
                 float* __restrict__ out) {
    extern __shared__ char smem_raw[];
    SmemLayout* sm = reinterpret_cast<SmemLayout*>(smem_raw);
    const int tid = threadIdx.x;
    const int g   = blockIdx.x;

    float* A = sm->buf0;
    float* B = sm->buf1;

    if (tid < 128) sm->cnt[tid] = 0;
    if (tid < 32)  sm->dhist[tid] = 0;
    __syncthreads();

    // ---- degree count
    const int* srcg = src + g * EDGES;
    const int* dstg = dst + g * EDGES;
    const int base = g * NODES;
    for (int e = tid; e < EDGES; e += NTHR) {
        int dl = dstg[e] - base;
        atomicAdd(&sm->cnt[dl], 1);
    }
    __syncthreads();

    int mydeg = 0;
    if (tid < 128) {
        mydeg = sm->cnt[tid];
        float d = fmaxf((float)mydeg, 1.f);
        sm->nA[tid]   = rsqrtf(d);
        sm->n2[tid]   = 1.0f / d;
        sm->invn[tid] = sqrtf(d);
    }
    if (tid < NODES)
        atomicAdd(&sm->dhist[mydeg < 31 ? mydeg : 31], 1);
    __syncthreads();
    if (tid == 0) {            // exclusive scan of 32 bins
        int acc = 0;
#pragma unroll
        for (int i = 0; i < 32; i++) {
            int t = sm->dhist[i];
            sm->dhist[i] = acc;
            acc += t;
        }
    }
    __syncthreads();
    if (tid < NODES) {         // counting-sort placement
        int p = atomicAdd(&sm->dhist[mydeg < 31 ? mydeg : 31], 1);
        sm->ord[p] = tid;
    }
    // inclusive scan over cnt -> rowptr
    for (int off = 1; off < 128; off <<= 1) {
        int t = 0;
        if (tid < 128 && tid >= off) t = sm->cnt[tid - off];
        __syncthreads();
        if (tid < 128 && tid >= off) sm->cnt[tid] += t;
        __syncthreads();
    }
    if (tid == 0) sm->rowptr[0] = 0;
    if (tid < NODES) sm->rowptr[tid + 1] = sm->cnt[tid];
    __syncthreads();
    if (tid < NODES) sm->cnt[tid] = sm->rowptr[tid];
    __syncthreads();
    for (int e = tid; e < EDGES; e += NTHR) {
        int sl = srcg[e] - base;
        int dl = dstg[e] - base;
        int pos = atomicAdd(&sm->cnt[dl], 1);
        sm->csr[pos] = (unsigned short)sl;
    }
    __syncthreads();

    // ---- load pre-scaled x~ = n (.) x into cols 0..73; zero cols 74..79
    {
        const float* xg = x + (size_t)g * (NODES * 74);
        for (int idx = tid; idx < NODES * 74; idx += NTHR) {
            int v = idx / 74;
            int c = idx - v * 74;
            A[v * ST + c] = xg[idx] * sm->nA[v];
        }
        for (int idx = tid; idx < NODES * 6; idx += NTHR) {
            int v = idx / 6;
            int c = 74 + (idx - v * 6);
            A[v * ST + c] = 0.f;
        }
    }
    __syncthreads();

    // ---- 5 TAGConv layers    PW KT NT DOUT            Wpad offset
    layer<80, 5, 9, 70>(A, B, g_Wpad +     0, b0, sm, tid);
    layer<72, 5, 9, 65>(B, A, g_Wpad + 17280, b1, sm, tid);
    layer<72, 5, 8, 60>(A, B, g_Wpad + 34560, b2, sm, tid);
    layer<64, 4, 7, 55>(B, A, g_Wpad + 49920, b3, sm, tid);
    layer<56, 4, 5, 37>(A, B, g_Wpad + 60672, b4, sm, tid);
    float* H = B;   // final h~ = n (.) h : rows<100, cols 0..39 (37..39 zero)

    // ---- gate = invn * (h~ @ gw) + gb ; softmax; pool
    float gval = -1e30f;
    if (tid < NODES) {
        float s = 0.f;
#pragma unroll
        for (int c = 0; c < 37; c++)
            s += H[tid * ST + c] * __ldg(gw + c);
        s = s * sm->invn[tid] + __ldg(gb);
        sm->gate[tid] = s;
        gval = s;
    }
    if (tid < 128) sm->red[tid] = gval;
    __syncthreads();
    for (int s = 64; s > 0; s >>= 1) {
        if (tid < s) sm->red[tid] = fmaxf(sm->red[tid], sm->red[tid + s]);
        __syncthreads();
    }
    float gmax = sm->red[0];
    __syncthreads();

    float ev = 0.f;
    if (tid < NODES) {
        ev = expf(sm->gate[tid] - gmax);
        sm->gate[tid] = ev * sm->invn[tid];   // fold invn for pooled h~ sum
    }
    if (tid < 128) sm->red[tid] = ev;
    __syncthreads();
    for (int s = 64; s > 0; s >>= 1) {
        if (tid < s) sm->red[tid] += sm->red[tid + s];
        __syncthreads();
    }
    float Z = sm->red[0];

    if (tid < 37) {
        float a = 0.f;
        for (int v = 0; v < NODES; v++)
            a += sm->gate[v] * H[v * ST + tid];
        out[g * 37 + tid] = a / Z;
    }
}

extern "C" void kernel_launch(void* const* d_in, const int* in_sizes, int n_in,
                              void* d_out, int out_size) {
    const float* x   = (const float*)d_in[0];
    const int*   src = (const int*)d_in[1];
    const int*   dst = (const int*)d_in[2];
    const float* W0 = (const float*)d_in[4];
    const float* b0 = (const float*)d_in[5];
    const float* W1 = (const float*)d_in[6];
    const float* b1 = (const float*)d_in[7];
    const float* W2 = (const float*)d_in[8];
    const float* b2 = (const float*)d_in[9];
    const float* W3 = (const float*)d_in[10];
    const float* b3 = (const float*)d_in[11];
    const float* W4 = (const float*)d_in[12];
    const float* b4 = (const float*)d_in[13];
    const float* gw = (const float*)d_in[14];
    const float* gb = (const float*)d_in[15];
    float* out = (float*)d_out;

    prep_weights<<<128, 256>>>(W0, W1, W2, W3, W4);

    const int smem_bytes = (int)sizeof(SmemLayout);
    cudaFuncSetAttribute(gnn_fused_kernel,
                         cudaFuncAttributeMaxDynamicSharedMemorySize,
                         smem_bytes);
    gnn_fused_kernel<<<5000, NTHR, smem_bytes>>>(
        x, src, dst,
        b0, b1, b2, b3, b4,
        gw, gb, out);
}